// round 16
// baseline (speedup 1.0000x reference)
#include <cuda_runtime.h>
#include <cstdint>

// Problem constants
#define NUM_USERS 100000
#define NUM_ITEMS 100000
#define EMB_K 6
#define BATCH 2048

#define N4      (NUM_USERS / 4)   // 25000 float4 per row
#define ROWS    8                 // batch rows per rowgroup
#define NSPLIT  4                 // column splits (finer tiles -> smaller tail)
#define THREADS 256
#define COLS4   (N4 / NSPLIT)     // 6250 float4 per split
#define ROWGROUPS (BATCH / ROWS)          // 256
#define GRID      (ROWGROUPS * NSPLIT)    // 1024

// Scratch: partial U_emb per split + per-rowgroup completion counters
__device__ float g_Upart[NSPLIT][BATCH][EMB_K];
__device__ unsigned int g_cnt[ROWGROUPS];

__global__ __launch_bounds__(THREADS, 2)   // cap regs at 128 -> 2 blocks/SM
void fused_kernel(const float4* __restrict__ x_user4,
                  const float4* __restrict__ Ww4,
                  const void*  __restrict__ x_item,
                  const float* __restrict__ H_w,
                  const float* __restrict__ W1, const float* __restrict__ b1,
                  const float* __restrict__ W2, const float* __restrict__ b2,
                  const float* __restrict__ W3,
                  float* __restrict__ out) {
    const int tid   = threadIdx.x;
    const int lane  = tid & 31;
    const int warp  = tid >> 5;
    const int bx    = blockIdx.x;
    const int split = bx & (NSPLIT - 1);
    const int rg    = bx >> 2;              // log2(NSPLIT)
    const int row0  = rg * ROWS;
    const int c0    = split * COLS4;
    const int c1    = c0 + COLS4;

    // ---------------- streaming GEMV (R3's proven inner loop) ----------------
    float acc[ROWS][EMB_K];
#pragma unroll
    for (int r = 0; r < ROWS; r++)
#pragma unroll
        for (int k = 0; k < EMB_K; k++)
            acc[r][k] = 0.0f;

    for (int i4 = c0 + tid; i4 < c1; i4 += THREADS) {
        float4 w[EMB_K];
#pragma unroll
        for (int k = 0; k < EMB_K; k++)
            w[k] = __ldg(&Ww4[k * N4 + i4]);

#pragma unroll
        for (int r = 0; r < ROWS; r++) {
            const float4 x = __ldg(&x_user4[(size_t)(row0 + r) * N4 + i4]);
#pragma unroll
            for (int k = 0; k < EMB_K; k++) {
                acc[r][k] = fmaf(x.x, w[k].x, acc[r][k]);
                acc[r][k] = fmaf(x.y, w[k].y, acc[r][k]);
                acc[r][k] = fmaf(x.z, w[k].z, acc[r][k]);
                acc[r][k] = fmaf(x.w, w[k].w, acc[r][k]);
            }
        }
    }

    // ---------------- block reduction -> partial U_emb ----------------
    __shared__ float sred[THREADS / 32][ROWS * EMB_K];   // 8 x 48 floats

#pragma unroll
    for (int r = 0; r < ROWS; r++) {
#pragma unroll
        for (int k = 0; k < EMB_K; k++) {
            float v = acc[r][k];
#pragma unroll
            for (int off = 16; off > 0; off >>= 1)
                v += __shfl_down_sync(0xffffffffu, v, off);
            if (lane == 0) sred[warp][r * EMB_K + k] = v;
        }
    }
    __syncthreads();

    if (tid < ROWS * EMB_K) {
        float s = 0.0f;
#pragma unroll
        for (int w2 = 0; w2 < THREADS / 32; w2++)
            s += sred[w2][tid];
        g_Upart[split][row0 + tid / EMB_K][tid % EMB_K] = s;
    }

    // ---------------- N-way handoff: last split-block runs the MLP ---------
    __shared__ int s_lastsplit;
    __threadfence();                 // publish this split's partials
    __syncthreads();
    if (tid == 0) {
        unsigned int old = atomicAdd(&g_cnt[rg], 1u);
        s_lastsplit = (old == NSPLIT - 1) ? 1 : 0;
    }
    __syncthreads();
    if (!s_lastsplit) return;

    if (tid == 0) g_cnt[rg] = 0;     // reset for next graph replay
    __threadfence();

    // ---------------- int64/int32 index detection (first 256 high-words) ---
    __shared__ int s_nz;
    if (tid == 0) s_nz = 0;
    __syncthreads();
    {
        // Reads first 2048 bytes: safe for int32 (8192 B) and int64 (16384 B).
        const unsigned int* p = (const unsigned int*)x_item;
        if (p[2 * tid + 1] != 0u) s_nz = 1;   // benign race
    }
    __syncthreads();
    const bool is64 = (s_nz == 0);

    // ---------------- MLP for this rowgroup's 8 batch rows ----------------
    if (tid < ROWS) {
        const int b = row0 + tid;
        long long idx;
        if (is64) idx = ((const long long*)x_item)[b];
        else      idx = (long long)(((const int*)x_item)[b]);

        float z[12];
#pragma unroll
        for (int k = 0; k < EMB_K; k++) {
            float s = 0.0f;
#pragma unroll
            for (int sp = 0; sp < NSPLIT; sp++)
                s += g_Upart[sp][b][k];
            z[k] = s;
        }
#pragma unroll
        for (int k = 0; k < EMB_K; k++)
            z[EMB_K + k] = __ldg(&H_w[(size_t)k * NUM_ITEMS + idx]);

        float h1[16];
#pragma unroll
        for (int j = 0; j < 16; j++) {
            float s = __ldg(&b1[j]);
#pragma unroll
            for (int i = 0; i < 12; i++)
                s = fmaf(z[i], __ldg(&W1[j * 12 + i]), s);
            h1[j] = fmaxf(s, 0.0f);
        }

        float h2[8];
#pragma unroll
        for (int j = 0; j < 8; j++) {
            float s = __ldg(&b2[j]);
#pragma unroll
            for (int i = 0; i < 16; i++)
                s = fmaf(h1[i], __ldg(&W2[j * 16 + i]), s);
            h2[j] = fmaxf(s, 0.0f);
        }

        float o = __ldg(&W3[8]);   // ones-column term
#pragma unroll
        for (int i = 0; i < 8; i++)
            o = fmaf(h2[i], __ldg(&W3[i]), o);

        out[b] = o;
    }
}

extern "C" void kernel_launch(void* const* d_in, const int* in_sizes, int n_in,
                              void* d_out, int out_size) {
    const float* x_user = (const float*)d_in[0];
    const void*  x_item = d_in[1];
    const float* W_w    = (const float*)d_in[2];
    const float* H_w    = (const float*)d_in[3];
    const float* W1     = (const float*)d_in[4];
    const float* b1     = (const float*)d_in[5];
    const float* W2     = (const float*)d_in[6];
    const float* b2     = (const float*)d_in[7];
    const float* W3     = (const float*)d_in[8];
    float* out          = (float*)d_out;

    fused_kernel<<<GRID, THREADS>>>(
        (const float4*)x_user, (const float4*)W_w, x_item, H_w,
        W1, b1, W2, b2, W3, out);
}

// round 17
// speedup vs baseline: 1.0560x; 1.0560x over previous
#include <cuda_runtime.h>
#include <cstdint>

// Problem constants
#define NUM_USERS 100000
#define NUM_ITEMS 100000
#define EMB_K 6
#define BATCH 2048

#define N4      (NUM_USERS / 4)   // 25000 float4 per row
#define ROWS    8                 // batch rows per rowgroup (proven)
#define NSPLIT  2                 // column splits (proven)
#define THREADS 256
#define COLS4   (N4 / NSPLIT)     // 12500 float4 per split
#define ROWGROUPS (BATCH / ROWS)          // 256
#define GRID      (ROWGROUPS * NSPLIT)    // 512  (proven)

// Scratch: partial U_emb per split + per-rowgroup completion counters
__device__ float g_Upart[NSPLIT][BATCH][EMB_K];
__device__ unsigned int g_cnt[ROWGROUPS];

__global__ __launch_bounds__(THREADS, 2)   // cap regs at 128 -> 2 blocks/SM
void fused_kernel(const float4* __restrict__ x_user4,
                  const float4* __restrict__ Ww4,
                  const void*  __restrict__ x_item,
                  const float* __restrict__ H_w,
                  const float* __restrict__ W1, const float* __restrict__ b1,
                  const float* __restrict__ W2, const float* __restrict__ b2,
                  const float* __restrict__ W3,
                  float* __restrict__ out) {
    const int tid   = threadIdx.x;
    const int lane  = tid & 31;
    const int warp  = tid >> 5;
    const int bx    = blockIdx.x;
    const int split = bx & (NSPLIT - 1);
    const int rg    = bx >> 1;
    const int row0  = rg * ROWS;
    const int c0    = split * COLS4;
    const int c1    = c0 + COLS4;

    // ---------------- streaming GEMV (R15's proven inner loop) --------------
    // x: single-use stream -> __ldcs (evict-first, keeps L1/L2 for W)
    // W: L2-resident, re-read by all blocks -> __ldg
    float acc[ROWS][EMB_K];
#pragma unroll
    for (int r = 0; r < ROWS; r++)
#pragma unroll
        for (int k = 0; k < EMB_K; k++)
            acc[r][k] = 0.0f;

    for (int i4 = c0 + tid; i4 < c1; i4 += THREADS) {
        float4 w[EMB_K];
#pragma unroll
        for (int k = 0; k < EMB_K; k++)
            w[k] = __ldg(&Ww4[k * N4 + i4]);

#pragma unroll
        for (int r = 0; r < ROWS; r++) {
            const float4 x = __ldcs(&x_user4[(size_t)(row0 + r) * N4 + i4]);
#pragma unroll
            for (int k = 0; k < EMB_K; k++) {
                acc[r][k] = fmaf(x.x, w[k].x, acc[r][k]);
                acc[r][k] = fmaf(x.y, w[k].y, acc[r][k]);
                acc[r][k] = fmaf(x.z, w[k].z, acc[r][k]);
                acc[r][k] = fmaf(x.w, w[k].w, acc[r][k]);
            }
        }
    }

    // ---------------- block reduction -> partial U_emb ----------------
    __shared__ float sred[THREADS / 32][ROWS * EMB_K];   // 8 x 48 floats

#pragma unroll
    for (int r = 0; r < ROWS; r++) {
#pragma unroll
        for (int k = 0; k < EMB_K; k++) {
            float v = acc[r][k];
#pragma unroll
            for (int off = 16; off > 0; off >>= 1)
                v += __shfl_down_sync(0xffffffffu, v, off);
            if (lane == 0) sred[warp][r * EMB_K + k] = v;
        }
    }
    __syncthreads();

    if (tid < ROWS * EMB_K) {
        float s = 0.0f;
#pragma unroll
        for (int w2 = 0; w2 < THREADS / 32; w2++)
            s += sred[w2][tid];
        g_Upart[split][row0 + tid / EMB_K][tid % EMB_K] = s;
    }

    // ---------------- pairwise handoff: second block runs the MLP ----------
    __shared__ int s_second;
    __threadfence();                 // publish this split's partials
    __syncthreads();
    if (tid == 0) {
        unsigned int old = atomicAdd(&g_cnt[rg], 1u);
        s_second = (old == NSPLIT - 1) ? 1 : 0;
    }
    __syncthreads();
    if (!s_second) return;

    if (tid == 0) g_cnt[rg] = 0;     // reset for next graph replay
    __threadfence();

    // ---------------- int64/int32 index detection (first 256 high-words) ---
    __shared__ int s_nz;
    if (tid == 0) s_nz = 0;
    __syncthreads();
    {
        // Reads first 2048 bytes: safe for int32 (8192 B) and int64 (16384 B).
        const unsigned int* p = (const unsigned int*)x_item;
        if (p[2 * tid + 1] != 0u) s_nz = 1;   // benign race
    }
    __syncthreads();
    const bool is64 = (s_nz == 0);

    // ---------------- MLP for this rowgroup's 8 batch rows ----------------
    if (tid < ROWS) {
        const int b = row0 + tid;
        long long idx;
        if (is64) idx = ((const long long*)x_item)[b];
        else      idx = (long long)(((const int*)x_item)[b]);

        float z[12];
#pragma unroll
        for (int k = 0; k < EMB_K; k++)
            z[k] = g_Upart[0][b][k] + g_Upart[1][b][k];
#pragma unroll
        for (int k = 0; k < EMB_K; k++)
            z[EMB_K + k] = __ldg(&H_w[(size_t)k * NUM_ITEMS + idx]);

        float h1[16];
#pragma unroll
        for (int j = 0; j < 16; j++) {
            float s = __ldg(&b1[j]);
#pragma unroll
            for (int i = 0; i < 12; i++)
                s = fmaf(z[i], __ldg(&W1[j * 12 + i]), s);
            h1[j] = fmaxf(s, 0.0f);
        }

        float h2[8];
#pragma unroll
        for (int j = 0; j < 8; j++) {
            float s = __ldg(&b2[j]);
#pragma unroll
            for (int i = 0; i < 16; i++)
                s = fmaf(h1[i], __ldg(&W2[j * 16 + i]), s);
            h2[j] = fmaxf(s, 0.0f);
        }

        float o = __ldg(&W3[8]);   // ones-column term
#pragma unroll
        for (int i = 0; i < 8; i++)
            o = fmaf(h2[i], __ldg(&W3[i]), o);

        out[b] = o;
    }
}

extern "C" void kernel_launch(void* const* d_in, const int* in_sizes, int n_in,
                              void* d_out, int out_size) {
    const float* x_user = (const float*)d_in[0];
    const void*  x_item = d_in[1];
    const float* W_w    = (const float*)d_in[2];
    const float* H_w    = (const float*)d_in[3];
    const float* W1     = (const float*)d_in[4];
    const float* b1     = (const float*)d_in[5];
    const float* W2     = (const float*)d_in[6];
    const float* b2     = (const float*)d_in[7];
    const float* W3     = (const float*)d_in[8];
    float* out          = (float*)d_out;

    fused_kernel<<<GRID, THREADS>>>(
        (const float4*)x_user, (const float4*)W_w, x_item, H_w,
        W1, b1, W2, b2, W3, out);
}